// round 1
// baseline (speedup 1.0000x reference)
#include <cuda_runtime.h>
#include <math.h>

#define BB   32
#define CC   256
#define HH   64
#define WW   64
#define MIPD 8
#define HIDD 256
#define OUTD 14

// ---------------- scratch (no allocations allowed) ----------------
__device__ float g_y [BB * CC * 128];   // [b][c][l]  l: 0..63 = xh, 64..127 = xw
__device__ float g_ah[BB * CC * HH];    // [b][c][h]
__device__ float g_aw[BB * CC * WW];    // [b][c][w]
__device__ float g_p [BB * CC];         // [b][c]

// ---------------- kernel 1: per-plane row/col means ----------------
__global__ __launch_bounds__(256) void k1_pool(const float* __restrict__ x) {
    int bc  = blockIdx.x;                       // b*256 + c
    int tid = threadIdx.x;
    int txq = tid & 15;                         // float4 index within row
    int ty  = tid >> 4;                         // 0..15

    const float4* plane = reinterpret_cast<const float4*>(x + (size_t)bc * (HH * WW));

    __shared__ float sh_h[64];
    __shared__ float sh_w[64];
    __shared__ float cpart[16][64];

    float c0 = 0.f, c1 = 0.f, c2 = 0.f, c3 = 0.f;
    #pragma unroll
    for (int r = 0; r < 4; r++) {
        int row = ty + 16 * r;
        float4 v = plane[row * 16 + txq];
        float rs = v.x + v.y + v.z + v.w;
        #pragma unroll
        for (int o = 8; o >= 1; o >>= 1)
            rs += __shfl_xor_sync(0xffffffffu, rs, o);
        if (txq == 0) sh_h[row] = rs * (1.0f / 64.0f);
        c0 += v.x; c1 += v.y; c2 += v.z; c3 += v.w;
    }
    cpart[ty][4 * txq + 0] = c0;
    cpart[ty][4 * txq + 1] = c1;
    cpart[ty][4 * txq + 2] = c2;
    cpart[ty][4 * txq + 3] = c3;
    __syncthreads();

    if (tid < 64) {
        float s = 0.f;
        #pragma unroll
        for (int t = 0; t < 16; t++) s += cpart[t][tid];
        sh_w[tid] = s * (1.0f / 64.0f);
    }
    __syncthreads();

    if (tid < 128) {
        float val = (tid < 64) ? sh_h[tid] : sh_w[tid - 64];
        g_y[bc * 128 + tid] = val;
    }
}

// ---------------- kernel 2: coordinate attention weights ----------------
__global__ __launch_bounds__(256) void k2_attn(
    const float* __restrict__ ca_w1,
    const float* __restrict__ bn_g, const float* __restrict__ bn_b,
    const float* __restrict__ bn_m, const float* __restrict__ bn_v,
    const float* __restrict__ ca_wh, const float* __restrict__ ca_ww)
{
    int b_idx = blockIdx.x;
    int tid   = threadIdx.x;

    __shared__ float s_w[2048];       // staged weights (8*256 or 256*8)
    __shared__ float s_y2[MIPD][128];

    for (int i = tid; i < 2048; i += 256) s_w[i] = ca_w1[i];
    __syncthreads();

    // y2[m][l] = sum_c ca_w1[m][c] * y[b][c][l] ; bn(axis=m) ; hswish
    int l  = tid & 127;
    int mg = tid >> 7;  // 0 or 1 -> m in [4*mg, 4*mg+4)
    float acc[4] = {0.f, 0.f, 0.f, 0.f};
    const float* yb = g_y + (size_t)b_idx * CC * 128 + l;
    for (int c = 0; c < CC; c++) {
        float yv = yb[c * 128];
        #pragma unroll
        for (int mi = 0; mi < 4; mi++)
            acc[mi] += s_w[(mg * 4 + mi) * 256 + c] * yv;
    }
    #pragma unroll
    for (int mi = 0; mi < 4; mi++) {
        int mm = mg * 4 + mi;
        float sc  = bn_g[mm] * rsqrtf(bn_v[mm] + 1e-5f);
        float val = (acc[mi] - bn_m[mm]) * sc + bn_b[mm];
        float t6  = fminf(fmaxf(val + 3.0f, 0.0f), 6.0f);
        s_y2[mm][l] = val * t6 * (1.0f / 6.0f);
    }
    __syncthreads();

    // a_h[c][h] = sigmoid(sum_m ca_wh[c][m] * y2[m][h])
    for (int i = tid; i < 2048; i += 256) s_w[i] = ca_wh[i];
    __syncthreads();
    {
        float* gah = g_ah + (size_t)b_idx * CC * HH;
        int hh = tid & 63;
        int co = tid >> 6;   // 0..3
        for (int cg = 0; cg < 64; cg++) {
            int c = cg * 4 + co;
            float s = 0.f;
            #pragma unroll
            for (int mm = 0; mm < MIPD; mm++)
                s += s_w[c * 8 + mm] * s_y2[mm][hh];
            gah[c * 64 + hh] = 1.0f / (1.0f + expf(-s));
        }
    }
    __syncthreads();

    // a_w[c][w] = sigmoid(sum_m ca_ww[c][m] * y2[m][64+w])
    for (int i = tid; i < 2048; i += 256) s_w[i] = ca_ww[i];
    __syncthreads();
    {
        float* gaw = g_aw + (size_t)b_idx * CC * WW;
        int hh = tid & 63;
        int co = tid >> 6;
        for (int cg = 0; cg < 64; cg++) {
            int c = cg * 4 + co;
            float s = 0.f;
            #pragma unroll
            for (int mm = 0; mm < MIPD; mm++)
                s += s_w[c * 8 + mm] * s_y2[mm][64 + hh];
            gaw[c * 64 + hh] = 1.0f / (1.0f + expf(-s));
        }
    }
}

// ---------------- kernel 3: weighted global pool ----------------
__global__ __launch_bounds__(256) void k3_wpool(const float* __restrict__ x) {
    int bc  = blockIdx.x;
    int tid = threadIdx.x;

    __shared__ float s_ah[64];
    __shared__ float s_aw[64];
    __shared__ float red[8];

    if (tid < 64)       s_ah[tid]      = g_ah[bc * 64 + tid];
    else if (tid < 128) s_aw[tid - 64] = g_aw[bc * 64 + (tid - 64)];
    __syncthreads();

    const float4* plane = reinterpret_cast<const float4*>(x + (size_t)bc * (HH * WW));
    int txq = tid & 15;
    int ty  = tid >> 4;

    float acc = 0.f;
    #pragma unroll
    for (int r = 0; r < 4; r++) {
        int row = ty + 16 * r;
        float4 v = plane[row * 16 + txq];
        float aw0 = s_aw[4 * txq + 0], aw1 = s_aw[4 * txq + 1];
        float aw2 = s_aw[4 * txq + 2], aw3 = s_aw[4 * txq + 3];
        acc += s_ah[row] * (v.x * aw0 + v.y * aw1 + v.z * aw2 + v.w * aw3);
    }
    #pragma unroll
    for (int o = 16; o >= 1; o >>= 1)
        acc += __shfl_xor_sync(0xffffffffu, acc, o);
    if ((tid & 31) == 0) red[tid >> 5] = acc;
    __syncthreads();
    if (tid == 0) {
        float s = 0.f;
        #pragma unroll
        for (int i = 0; i < 8; i++) s += red[i];
        g_p[bc] = s * (1.0f / 4096.0f);
    }
}

// ---------------- helpers for kernel 4 ----------------
__device__ __forceinline__ float softplus_f(float x) {
    return fmaxf(x, 0.0f) + log1pf(expf(-fabsf(x)));
}

// Exact port of LAPACK SLAEV2: matrix [[a,b],[b,c]].
// Returns rt1 (eigenvalue of larger |.|), rt2, and (cs1,sn1) = unit eigenvector of rt1.
__device__ void slaev2(float a, float b, float c,
                       float& rt1, float& rt2, float& cs1, float& sn1) {
    float sm  = a + c;
    float df  = a - c;
    float adf = fabsf(df);
    float tb  = b + b;
    float ab  = fabsf(tb);
    float acmx, acmn;
    if (fabsf(a) > fabsf(c)) { acmx = a; acmn = c; }
    else                     { acmx = c; acmn = a; }
    float rt;
    if      (adf > ab) { float q = ab / adf; rt = adf * sqrtf(1.0f + q * q); }
    else if (adf < ab) { float q = adf / ab; rt = ab  * sqrtf(1.0f + q * q); }
    else               { rt = ab * sqrtf(2.0f); }

    int sgn1;
    if (sm < 0.0f) {
        rt1 = 0.5f * (sm - rt); sgn1 = -1;
        rt2 = (acmx / rt1) * acmn - (b / rt1) * b;
    } else if (sm > 0.0f) {
        rt1 = 0.5f * (sm + rt); sgn1 = 1;
        rt2 = (acmx / rt1) * acmn - (b / rt1) * b;
    } else {
        rt1 = 0.5f * rt; rt2 = -0.5f * rt; sgn1 = 1;
    }

    float cs; int sgn2;
    if (df >= 0.0f) { cs = df + rt; sgn2 = 1; }
    else            { cs = df - rt; sgn2 = -1; }
    float acs = fabsf(cs);
    if (acs > ab) {
        float ct = -tb / cs;
        sn1 = 1.0f / sqrtf(1.0f + ct * ct);
        cs1 = ct * sn1;
    } else {
        if (ab == 0.0f) { cs1 = 1.0f; sn1 = 0.0f; }
        else {
            float tn = -cs / tb;
            cs1 = 1.0f / sqrtf(1.0f + tn * tn);
            sn1 = tn * cs1;
        }
    }
    if (sgn1 == sgn2) { float tn = cs1; cs1 = -sn1; sn1 = tn; }
}

// ---------------- kernel 4: MLP head + ellipse geometry ----------------
__global__ __launch_bounds__(256) void k4_head(
    const float* __restrict__ fc1_w,  const float* __restrict__ fc1_b,
    const float* __restrict__ bn1_g,  const float* __restrict__ bn1_b,
    const float* __restrict__ bn1_m,  const float* __restrict__ bn1_v,
    const float* __restrict__ fco_w,  const float* __restrict__ fco_b,
    const float* __restrict__ Kmat,   const float* __restrict__ iris_r,
    float* __restrict__ out)
{
    int b_idx = blockIdx.x;
    int tid   = threadIdx.x;

    __shared__ float s_p[HIDD];
    __shared__ float s_h[HIDD];
    __shared__ float s_raw[OUTD];

    s_p[tid] = g_p[b_idx * CC + tid];
    __syncthreads();

    // hdd = relu(bn1(p @ fc1_w^T + fc1_b))
    {
        const float4* wrow = reinterpret_cast<const float4*>(fc1_w + (size_t)tid * 256);
        const float4* pp   = reinterpret_cast<const float4*>(s_p);
        float acc = fc1_b[tid];
        #pragma unroll 8
        for (int c4 = 0; c4 < 64; c4++) {
            float4 w = wrow[c4];
            float4 p = pp[c4];
            acc += w.x * p.x + w.y * p.y + w.z * p.z + w.w * p.w;
        }
        float sc  = bn1_g[tid] * rsqrtf(bn1_v[tid] + 1e-5f);
        float val = (acc - bn1_m[tid]) * sc + bn1_b[tid];
        s_h[tid] = fmaxf(val, 0.0f);
    }
    __syncthreads();

    // raw = hdd @ fc_out^T + b
    if (tid < OUTD) {
        const float4* wrow = reinterpret_cast<const float4*>(fco_w + (size_t)tid * 256);
        const float4* hh   = reinterpret_cast<const float4*>(s_h);
        float acc = fco_b[tid];
        #pragma unroll 8
        for (int c4 = 0; c4 < 64; c4++) {
            float4 w = wrow[c4];
            float4 h = hh[c4];
            acc += w.x * h.x + w.y * h.y + w.z * h.z + w.w * h.w;
        }
        s_raw[tid] = acc;
    }
    __syncthreads();

    // geometry, one thread per ellipse e in {0,1}
    if (tid < 2) {
        const float* t  = s_raw + 7 * tid;
        const float* Kb = Kmat + b_idx * 9;
        float R = iris_r[b_idx];
        int be = b_idx * 2 + tid;

        float cx = t[0], cy = t[1];
        float ea = softplus_f(t[2]) + 1e-6f;
        float eb = softplus_f(t[3]) + 1e-6f;
        float n45 = sqrtf(t[4] * t[4] + t[5] * t[5]);
        float cth = t[4] / (n45 + 1e-8f);
        float sth = t[5] / (n45 + 1e-8f);
        float delta = 0.3f * tanhf(t[6]);

        // ellipse output
        out[be * 6 + 0] = cx;  out[be * 6 + 1] = cy;
        out[be * 6 + 2] = ea;  out[be * 6 + 3] = eb;
        out[be * 6 + 4] = cth; out[be * 6 + 5] = sth;
        out[384 + be] = delta;

        float theta = atan2f(sth, cth);
        float ct = cosf(theta), st = sinf(theta);
        float ia2 = 1.0f / (ea * ea), ib2 = 1.0f / (eb * eb);
        float A11 = ct * ct * ia2 + st * st * ib2;
        float A22 = st * st * ia2 + ct * ct * ib2;
        float A12 = ct * st * (ia2 - ib2);
        float ax  = A11 * cx + A12 * cy;
        float ay  = A12 * cx + A22 * cy;
        float cAc = A11 * cx * cx + 2.0f * A12 * cx * cy + A22 * cy * cy;

        float Cm[3][3] = {{A11, A12, -ax}, {A12, A22, -ay}, {-ax, -ay, cAc - 1.0f}};
        float Kl[3][3];
        #pragma unroll
        for (int r = 0; r < 3; r++)
            #pragma unroll
            for (int c = 0; c < 3; c++)
                Kl[r][c] = Kb[r * 3 + c];

        float T[3][3], Cn[3][3];
        #pragma unroll
        for (int j = 0; j < 3; j++)
            #pragma unroll
            for (int l = 0; l < 3; l++)
                T[j][l] = Cm[j][0] * Kl[0][l] + Cm[j][1] * Kl[1][l] + Cm[j][2] * Kl[2][l];
        #pragma unroll
        for (int i = 0; i < 3; i++)
            #pragma unroll
            for (int l = 0; l < 3; l++)
                Cn[i][l] = Kl[0][i] * T[0][l] + Kl[1][i] * T[1][l] + Kl[2][i] * T[2][l];

        // mu = solve(A, -u), A = Cn[:2,:2], u = Cn[:2,2]
        float u0 = Cn[0][2], u1 = Cn[1][2];
        float det = Cn[0][0] * Cn[1][1] - Cn[0][1] * Cn[1][0];
        float mu0 = (-u0 * Cn[1][1] + u1 * Cn[0][1]) / det;
        float mu1 = (-u1 * Cn[0][0] + u0 * Cn[1][0]) / det;

        // eigh on symmetrized lower-triangle 2x2 (matches jax eigh: symmetrize + LAPACK)
        float aa = Cn[0][0];
        float bb = 0.5f * (Cn[0][1] + Cn[1][0]);
        float cc = Cn[1][1];
        float rt1, rt2, cs1, sn1;
        slaev2(aa, bb, cc, rt1, rt2, cs1, sn1);
        // DSTEQR applies Z = P^T (cols: (cs1,sn1) for rt1, (-sn1,cs1) for rt2),
        // then sorts eigenvalues ascending with column swap.
        float lam0, lam1, v0, v1;
        if (rt1 >= rt2) { lam0 = rt2; lam1 = rt1; v0 = -sn1; v1 = cs1; }
        else            { lam0 = rt1; lam1 = rt2; v0 = cs1;  v1 = sn1; }

        float a_n = 1.0f / sqrtf(fmaxf(lam0, 1e-12f));
        float b_n = 1.0f / sqrtf(fmaxf(lam1, 1e-12f));
        float theta_n = atan2f(v1, v0);
        a_n = fmaxf(a_n, 1e-6f);

        float z = fminf(fmaxf(R / a_n, 0.5f), 1000.0f);
        float rn = sqrtf(mu0 * mu0 + mu1 * mu1 + 1.0f) + 1e-8f;
        float ic0 = (mu0 / rn) * z, ic1 = (mu1 / rn) * z, ic2 = (1.0f / rn) * z;

        float ctl = fminf(fmaxf(b_n / a_n, 0.0f), 1.0f);
        float stl = sqrtf(fmaxf(1.0f - ctl * ctl, 0.0f));

        float kx = cosf(theta_n), ky = sinf(theta_n);
        float kn = sqrtf(kx * kx + ky * ky) + 1e-8f;
        kx /= kn; ky /= kn;

        float nx = ky * stl, ny = -kx * stl, nz = ctl;
        float nn = sqrtf(nx * nx + ny * ny + nz * nz) + 1e-8f;
        nx /= nn; ny /= nn; nz /= nn;

        // outputs: iris_center @448, normal @640, pupil @832, z @1024
        out[448 + be * 3 + 0] = ic0;
        out[448 + be * 3 + 1] = ic1;
        out[448 + be * 3 + 2] = ic2;
        out[640 + be * 3 + 0] = nx;
        out[640 + be * 3 + 1] = ny;
        out[640 + be * 3 + 2] = nz;
        out[832 + be * 3 + 0] = ic0 + delta * nx;
        out[832 + be * 3 + 1] = ic1 + delta * ny;
        out[832 + be * 3 + 2] = ic2 + delta * nz;
        out[1024 + be] = z;
    }
}

// ---------------- launch ----------------
extern "C" void kernel_launch(void* const* d_in, const int* in_sizes, int n_in,
                              void* d_out, int out_size) {
    const float* x      = (const float*)d_in[0];
    const float* K      = (const float*)d_in[1];
    const float* iris_r = (const float*)d_in[2];
    const float* ca_w1  = (const float*)d_in[3];
    const float* ca_g   = (const float*)d_in[4];
    const float* ca_b   = (const float*)d_in[5];
    const float* ca_m   = (const float*)d_in[6];
    const float* ca_v   = (const float*)d_in[7];
    const float* ca_wh  = (const float*)d_in[8];
    const float* ca_ww  = (const float*)d_in[9];
    const float* fc1_w  = (const float*)d_in[10];
    const float* fc1_b  = (const float*)d_in[11];
    const float* bn1_g  = (const float*)d_in[12];
    const float* bn1_b  = (const float*)d_in[13];
    const float* bn1_m  = (const float*)d_in[14];
    const float* bn1_v  = (const float*)d_in[15];
    const float* fco_w  = (const float*)d_in[16];
    const float* fco_b  = (const float*)d_in[17];
    float* out = (float*)d_out;

    k1_pool<<<BB * CC, 256>>>(x);
    k2_attn<<<BB, 256>>>(ca_w1, ca_g, ca_b, ca_m, ca_v, ca_wh, ca_ww);
    k3_wpool<<<BB * CC, 256>>>(x);
    k4_head<<<BB, 256>>>(fc1_w, fc1_b, bn1_g, bn1_b, bn1_m, bn1_v,
                         fco_w, fco_b, K, iris_r, out);
}

// round 6
// speedup vs baseline: 1.2145x; 1.2145x over previous
#include <cuda_runtime.h>
#include <math.h>

#define BB   32
#define CC   256
#define HH   64
#define WW   64
#define MIPD 8
#define HIDD 256
#define OUTD 14

// ---------------- scratch (no allocations allowed) ----------------
__device__ float g_y  [BB * CC * 128];   // [b][c][l]  l: 0..63 = xh, 64..127 = xw
__device__ float g_y2 [BB * MIPD * 128]; // [b][m][l]  post-bn-hswish mid features
__device__ float g_p  [BB * CC];         // [b][c]

// ---------------- kernel 1: per-plane row/col means ----------------
__global__ __launch_bounds__(256) void k1_pool(const float* __restrict__ x) {
    int bc  = blockIdx.x;                       // b*256 + c
    int tid = threadIdx.x;
    int txq = tid & 15;                         // float4 index within row
    int ty  = tid >> 4;                         // 0..15

    const float4* plane = reinterpret_cast<const float4*>(x + (size_t)bc * (HH * WW));

    __shared__ float sh_h[64];
    __shared__ float sh_w[64];
    __shared__ float cpart[16][64];

    float c0 = 0.f, c1 = 0.f, c2 = 0.f, c3 = 0.f;
    #pragma unroll
    for (int r = 0; r < 4; r++) {
        int row = ty + 16 * r;
        float4 v = plane[row * 16 + txq];
        float rs = v.x + v.y + v.z + v.w;
        #pragma unroll
        for (int o = 8; o >= 1; o >>= 1)
            rs += __shfl_xor_sync(0xffffffffu, rs, o);
        if (txq == 0) sh_h[row] = rs * (1.0f / 64.0f);
        c0 += v.x; c1 += v.y; c2 += v.z; c3 += v.w;
    }
    cpart[ty][4 * txq + 0] = c0;
    cpart[ty][4 * txq + 1] = c1;
    cpart[ty][4 * txq + 2] = c2;
    cpart[ty][4 * txq + 3] = c3;
    __syncthreads();

    if (tid < 64) {
        float s = 0.f;
        #pragma unroll
        for (int t = 0; t < 16; t++) s += cpart[t][tid];
        sh_w[tid] = s * (1.0f / 64.0f);
    }
    __syncthreads();

    if (tid < 128) {
        float val = (tid < 64) ? sh_h[tid] : sh_w[tid - 64];
        g_y[bc * 128 + tid] = val;
    }
}

// ---------------- kernel 2: mid features y2 only ----------------
__global__ __launch_bounds__(256) void k2_mid(
    const float* __restrict__ ca_w1,
    const float* __restrict__ bn_g, const float* __restrict__ bn_b,
    const float* __restrict__ bn_m, const float* __restrict__ bn_v)
{
    int b_idx = blockIdx.x;
    int tid   = threadIdx.x;

    __shared__ float s_w[2048];       // ca_w1 (8 x 256)
    for (int i = tid; i < 2048; i += 256) s_w[i] = ca_w1[i];
    __syncthreads();

    // y2[m][l] = hswish(bn(sum_c ca_w1[m][c] * y[b][c][l]))
    int l  = tid & 127;
    int mg = tid >> 7;  // 0 or 1 -> m in [4*mg, 4*mg+4)
    float acc[4] = {0.f, 0.f, 0.f, 0.f};
    const float* yb = g_y + (size_t)b_idx * CC * 128 + l;
    #pragma unroll 4
    for (int c = 0; c < CC; c++) {
        float yv = yb[c * 128];
        #pragma unroll
        for (int mi = 0; mi < 4; mi++)
            acc[mi] += s_w[(mg * 4 + mi) * 256 + c] * yv;
    }
    float* out = g_y2 + (size_t)b_idx * MIPD * 128;
    #pragma unroll
    for (int mi = 0; mi < 4; mi++) {
        int mm = mg * 4 + mi;
        float sc  = bn_g[mm] * rsqrtf(bn_v[mm] + 1e-5f);
        float val = (acc[mi] - bn_m[mm]) * sc + bn_b[mm];
        float t6  = fminf(fmaxf(val + 3.0f, 0.0f), 6.0f);
        out[mm * 128 + l] = val * t6 * (1.0f / 6.0f);
    }
}

// ---------------- kernel 3: attention + weighted pool (fused) ----------------
__global__ __launch_bounds__(256) void k3_wpool(
    const float* __restrict__ x,
    const float* __restrict__ ca_wh, const float* __restrict__ ca_ww)
{
    int bc    = blockIdx.x;
    int b_idx = bc >> 8;
    int c_idx = bc & 255;
    int tid   = threadIdx.x;

    __shared__ float s_y2[MIPD * 128];
    __shared__ float s_a[128];         // [0:64]=a_h, [64:128]=a_w
    __shared__ float red[8];

    // stage y2[b] (4KB); 256 threads x 4 floats
    {
        const float* src = g_y2 + (size_t)b_idx * MIPD * 128;
        #pragma unroll
        for (int i = 0; i < 4; i++)
            s_y2[tid + 256 * i] = src[tid + 256 * i];
    }
    __syncthreads();

    // attention: s_a[l] = sigmoid(sum_m w[c][m] * y2[m][l])
    if (tid < 128) {
        const float* wrow = (tid < 64) ? (ca_wh + c_idx * MIPD)
                                       : (ca_ww + c_idx * MIPD);
        int l = tid;
        float s = 0.f;
        #pragma unroll
        for (int m = 0; m < MIPD; m++)
            s += __ldg(wrow + m) * s_y2[m * 128 + l];
        s_a[tid] = 1.0f / (1.0f + __expf(-s));
    }
    __syncthreads();

    const float4* plane = reinterpret_cast<const float4*>(x + (size_t)bc * (HH * WW));
    int txq = tid & 15;
    int ty  = tid >> 4;

    float aw0 = s_a[64 + 4 * txq + 0], aw1 = s_a[64 + 4 * txq + 1];
    float aw2 = s_a[64 + 4 * txq + 2], aw3 = s_a[64 + 4 * txq + 3];

    float acc = 0.f;
    #pragma unroll
    for (int r = 0; r < 4; r++) {
        int row = ty + 16 * r;
        float4 v = plane[row * 16 + txq];
        acc += s_a[row] * (v.x * aw0 + v.y * aw1 + v.z * aw2 + v.w * aw3);
    }
    #pragma unroll
    for (int o = 16; o >= 1; o >>= 1)
        acc += __shfl_xor_sync(0xffffffffu, acc, o);
    if ((tid & 31) == 0) red[tid >> 5] = acc;
    __syncthreads();
    if (tid == 0) {
        float s = 0.f;
        #pragma unroll
        for (int i = 0; i < 8; i++) s += red[i];
        g_p[bc] = s * (1.0f / 4096.0f);
    }
}

// ---------------- helpers for kernel 4 ----------------
__device__ __forceinline__ float softplus_f(float x) {
    return fmaxf(x, 0.0f) + log1pf(__expf(-fabsf(x)));
}

// Exact port of LAPACK SLAEV2: matrix [[a,b],[b,c]].
__device__ void slaev2(float a, float b, float c,
                       float& rt1, float& rt2, float& cs1, float& sn1) {
    float sm  = a + c;
    float df  = a - c;
    float adf = fabsf(df);
    float tb  = b + b;
    float ab  = fabsf(tb);
    float acmx, acmn;
    if (fabsf(a) > fabsf(c)) { acmx = a; acmn = c; }
    else                     { acmx = c; acmn = a; }
    float rt;
    if      (adf > ab) { float q = ab / adf; rt = adf * sqrtf(1.0f + q * q); }
    else if (adf < ab) { float q = adf / ab; rt = ab  * sqrtf(1.0f + q * q); }
    else               { rt = ab * sqrtf(2.0f); }

    int sgn1;
    if (sm < 0.0f) {
        rt1 = 0.5f * (sm - rt); sgn1 = -1;
        rt2 = (acmx / rt1) * acmn - (b / rt1) * b;
    } else if (sm > 0.0f) {
        rt1 = 0.5f * (sm + rt); sgn1 = 1;
        rt2 = (acmx / rt1) * acmn - (b / rt1) * b;
    } else {
        rt1 = 0.5f * rt; rt2 = -0.5f * rt; sgn1 = 1;
    }

    float cs; int sgn2;
    if (df >= 0.0f) { cs = df + rt; sgn2 = 1; }
    else            { cs = df - rt; sgn2 = -1; }
    float acs = fabsf(cs);
    if (acs > ab) {
        float ct = -tb / cs;
        sn1 = 1.0f / sqrtf(1.0f + ct * ct);
        cs1 = ct * sn1;
    } else {
        if (ab == 0.0f) { cs1 = 1.0f; sn1 = 0.0f; }
        else {
            float tn = -cs / tb;
            cs1 = 1.0f / sqrtf(1.0f + tn * tn);
            sn1 = tn * cs1;
        }
    }
    if (sgn1 == sgn2) { float tn = cs1; cs1 = -sn1; sn1 = tn; }
}

// ---------------- kernel 4: MLP head + ellipse geometry ----------------
__global__ __launch_bounds__(256) void k4_head(
    const float* __restrict__ fc1_w,  const float* __restrict__ fc1_b,
    const float* __restrict__ bn1_g,  const float* __restrict__ bn1_b,
    const float* __restrict__ bn1_m,  const float* __restrict__ bn1_v,
    const float* __restrict__ fco_w,  const float* __restrict__ fco_b,
    const float* __restrict__ Kmat,   const float* __restrict__ iris_r,
    float* __restrict__ out)
{
    int b_idx = blockIdx.x;
    int tid   = threadIdx.x;

    __shared__ float s_p[HIDD];
    __shared__ float s_h[HIDD];
    __shared__ float s_raw[OUTD];

    s_p[tid] = g_p[b_idx * CC + tid];
    __syncthreads();

    // hdd = relu(bn1(p @ fc1_w^T + fc1_b))  -- 4 independent accumulators
    {
        const float4* wrow = reinterpret_cast<const float4*>(fc1_w + (size_t)tid * 256);
        const float4* pp   = reinterpret_cast<const float4*>(s_p);
        float a0 = 0.f, a1 = 0.f, a2 = 0.f, a3 = 0.f;
        #pragma unroll
        for (int c4 = 0; c4 < 64; c4 += 4) {
            float4 w0 = wrow[c4 + 0], p0 = pp[c4 + 0];
            float4 w1 = wrow[c4 + 1], p1 = pp[c4 + 1];
            float4 w2 = wrow[c4 + 2], p2 = pp[c4 + 2];
            float4 w3 = wrow[c4 + 3], p3 = pp[c4 + 3];
            a0 += w0.x * p0.x + w0.y * p0.y + w0.z * p0.z + w0.w * p0.w;
            a1 += w1.x * p1.x + w1.y * p1.y + w1.z * p1.z + w1.w * p1.w;
            a2 += w2.x * p2.x + w2.y * p2.y + w2.z * p2.z + w2.w * p2.w;
            a3 += w3.x * p3.x + w3.y * p3.y + w3.z * p3.z + w3.w * p3.w;
        }
        float acc = ((a0 + a1) + (a2 + a3)) + fc1_b[tid];
        float sc  = bn1_g[tid] * rsqrtf(bn1_v[tid] + 1e-5f);
        float val = (acc - bn1_m[tid]) * sc + bn1_b[tid];
        s_h[tid] = fmaxf(val, 0.0f);
    }
    __syncthreads();

    // raw = hdd @ fc_out^T + b  -- 8 lanes per row, shuffle-reduce.
    // NOTE: branch must cover WHOLE warps (tid<128, warps 0-3) so every lane
    // named in the shuffle mask executes the shuffle. Rows 14,15 are phantom:
    // weight index clamped in-bounds, result discarded.
    if (tid < 128) {
        int r  = tid >> 3;                    // 0..15 (14,15 phantom)
        int j  = tid & 7;
        int rc = (r < OUTD) ? r : (OUTD - 1); // clamp for in-bounds loads
        const float4* wrow = reinterpret_cast<const float4*>(fco_w + (size_t)rc * 256);
        const float4* hh   = reinterpret_cast<const float4*>(s_h);
        float acc = 0.f;
        #pragma unroll
        for (int q = 0; q < 8; q++) {
            float4 w = wrow[j * 8 + q];
            float4 h = hh[j * 8 + q];
            acc += w.x * h.x + w.y * h.y + w.z * h.z + w.w * h.w;
        }
        acc += __shfl_xor_sync(0xffffffffu, acc, 1);
        acc += __shfl_xor_sync(0xffffffffu, acc, 2);
        acc += __shfl_xor_sync(0xffffffffu, acc, 4);
        if (j == 0 && r < OUTD) s_raw[r] = acc + fco_b[r];
    }
    __syncthreads();

    // geometry, one thread per ellipse e in {0,1}
    if (tid < 2) {
        const float* t  = s_raw + 7 * tid;
        const float* Kb = Kmat + b_idx * 9;
        float R = iris_r[b_idx];
        int be = b_idx * 2 + tid;

        float cx = t[0], cy = t[1];
        float ea = softplus_f(t[2]) + 1e-6f;
        float eb = softplus_f(t[3]) + 1e-6f;
        float n45 = sqrtf(t[4] * t[4] + t[5] * t[5]);
        float cth = t[4] / (n45 + 1e-8f);
        float sth = t[5] / (n45 + 1e-8f);
        float e7 = __expf(2.0f * t[6]);
        float delta = 0.3f * ((e7 - 1.0f) / (e7 + 1.0f));   // tanh

        out[be * 6 + 0] = cx;  out[be * 6 + 1] = cy;
        out[be * 6 + 2] = ea;  out[be * 6 + 3] = eb;
        out[be * 6 + 4] = cth; out[be * 6 + 5] = sth;
        out[384 + be] = delta;

        // cos(atan2(sth,cth)) == cth, sin == sth (unit vector) -> skip trig
        float ct = cth, st = sth;
        float ia2 = 1.0f / (ea * ea), ib2 = 1.0f / (eb * eb);
        float A11 = ct * ct * ia2 + st * st * ib2;
        float A22 = st * st * ia2 + ct * ct * ib2;
        float A12 = ct * st * (ia2 - ib2);
        float ax  = A11 * cx + A12 * cy;
        float ay  = A12 * cx + A22 * cy;
        float cAc = A11 * cx * cx + 2.0f * A12 * cx * cy + A22 * cy * cy;

        float Cm[3][3] = {{A11, A12, -ax}, {A12, A22, -ay}, {-ax, -ay, cAc - 1.0f}};
        float Kl[3][3];
        #pragma unroll
        for (int r = 0; r < 3; r++)
            #pragma unroll
            for (int c = 0; c < 3; c++)
                Kl[r][c] = Kb[r * 3 + c];

        float T[3][3], Cn[3][3];
        #pragma unroll
        for (int j = 0; j < 3; j++)
            #pragma unroll
            for (int l = 0; l < 3; l++)
                T[j][l] = Cm[j][0] * Kl[0][l] + Cm[j][1] * Kl[1][l] + Cm[j][2] * Kl[2][l];
        #pragma unroll
        for (int i = 0; i < 3; i++)
            #pragma unroll
            for (int l = 0; l < 3; l++)
                Cn[i][l] = Kl[0][i] * T[0][l] + Kl[1][i] * T[1][l] + Kl[2][i] * T[2][l];

        float u0 = Cn[0][2], u1 = Cn[1][2];
        float det = Cn[0][0] * Cn[1][1] - Cn[0][1] * Cn[1][0];
        float mu0 = (-u0 * Cn[1][1] + u1 * Cn[0][1]) / det;
        float mu1 = (-u1 * Cn[0][0] + u0 * Cn[1][0]) / det;

        float aa = Cn[0][0];
        float bb = 0.5f * (Cn[0][1] + Cn[1][0]);
        float cc = Cn[1][1];
        float rt1, rt2, cs1, sn1;
        slaev2(aa, bb, cc, rt1, rt2, cs1, sn1);
        float lam0, lam1, v0, v1;
        if (rt1 >= rt2) { lam0 = rt2; lam1 = rt1; v0 = -sn1; v1 = cs1; }
        else            { lam0 = rt1; lam1 = rt2; v0 = cs1;  v1 = sn1; }

        float a_n = 1.0f / sqrtf(fmaxf(lam0, 1e-12f));
        float b_n = 1.0f / sqrtf(fmaxf(lam1, 1e-12f));
        a_n = fmaxf(a_n, 1e-6f);

        float z = fminf(fmaxf(R / a_n, 0.5f), 1000.0f);
        float rn = sqrtf(mu0 * mu0 + mu1 * mu1 + 1.0f) + 1e-8f;
        float ic0 = (mu0 / rn) * z, ic1 = (mu1 / rn) * z, ic2 = (1.0f / rn) * z;

        float ctl = fminf(fmaxf(b_n / a_n, 0.0f), 1.0f);
        float stl = sqrtf(fmaxf(1.0f - ctl * ctl, 0.0f));

        // k = normalize((cos(theta_n), sin(theta_n), 0)) == (v0, v1) normalized
        float kn = sqrtf(v0 * v0 + v1 * v1) + 1e-8f;
        float kx = v0 / kn, ky = v1 / kn;

        float nx = ky * stl, ny = -kx * stl, nz = ctl;
        float nn = sqrtf(nx * nx + ny * ny + nz * nz) + 1e-8f;
        nx /= nn; ny /= nn; nz /= nn;

        out[448 + be * 3 + 0] = ic0;
        out[448 + be * 3 + 1] = ic1;
        out[448 + be * 3 + 2] = ic2;
        out[640 + be * 3 + 0] = nx;
        out[640 + be * 3 + 1] = ny;
        out[640 + be * 3 + 2] = nz;
        out[832 + be * 3 + 0] = ic0 + delta * nx;
        out[832 + be * 3 + 1] = ic1 + delta * ny;
        out[832 + be * 3 + 2] = ic2 + delta * nz;
        out[1024 + be] = z;
    }
}

// ---------------- launch ----------------
extern "C" void kernel_launch(void* const* d_in, const int* in_sizes, int n_in,
                              void* d_out, int out_size) {
    const float* x      = (const float*)d_in[0];
    const float* K      = (const float*)d_in[1];
    const float* iris_r = (const float*)d_in[2];
    const float* ca_w1  = (const float*)d_in[3];
    const float* ca_g   = (const float*)d_in[4];
    const float* ca_b   = (const float*)d_in[5];
    const float* ca_m   = (const float*)d_in[6];
    const float* ca_v   = (const float*)d_in[7];
    const float* ca_wh  = (const float*)d_in[8];
    const float* ca_ww  = (const float*)d_in[9];
    const float* fc1_w  = (const float*)d_in[10];
    const float* fc1_b  = (const float*)d_in[11];
    const float* bn1_g  = (const float*)d_in[12];
    const float* bn1_b  = (const float*)d_in[13];
    const float* bn1_m  = (const float*)d_in[14];
    const float* bn1_v  = (const float*)d_in[15];
    const float* fco_w  = (const float*)d_in[16];
    const float* fco_b  = (const float*)d_in[17];
    float* out = (float*)d_out;

    k1_pool<<<BB * CC, 256>>>(x);
    k2_mid<<<BB, 256>>>(ca_w1, ca_g, ca_b, ca_m, ca_v);
    k3_wpool<<<BB * CC, 256>>>(x, ca_wh, ca_ww);
    k4_head<<<BB, 256>>>(fc1_w, fc1_b, bn1_g, bn1_b, bn1_m, bn1_v,
                         fco_w, fco_b, K, iris_r, out);
}

// round 7
// speedup vs baseline: 1.2956x; 1.0667x over previous
#include <cuda_runtime.h>
#include <math.h>

#define BB   32
#define CC   256
#define HH   64
#define WW   64
#define MIPD 8
#define HIDD 256
#define OUTD 14

// ---------------- scratch (no allocations allowed) ----------------
__device__ float g_y  [BB * CC * 128];   // [b][c][l]  l: 0..63 = xh, 64..127 = xw
__device__ float g_y2 [BB * MIPD * 128]; // [b][m][l]  post-bn-hswish mid features
__device__ float g_p  [BB * CC];         // [b][c]

// ---------------- kernel 1: per-plane row/col means (2 planes/block) ----------------
__global__ __launch_bounds__(256) void k1_pool(const float* __restrict__ x) {
    int bc0 = blockIdx.x * 2;
    int tid = threadIdx.x;
    int txq = tid & 15;                         // float4 index within row
    int ty  = tid >> 4;                         // 0..15

    const float4* pl0 = reinterpret_cast<const float4*>(x + (size_t)bc0 * (HH * WW));
    const float4* pl1 = pl0 + 1024;

    __shared__ float sh_h[2][64];
    __shared__ float sh_w[2][64];
    __shared__ float cpart[2][16][64];

    float c00 = 0.f, c01 = 0.f, c02 = 0.f, c03 = 0.f;
    float c10 = 0.f, c11 = 0.f, c12 = 0.f, c13 = 0.f;
    #pragma unroll
    for (int r = 0; r < 4; r++) {
        int row = ty + 16 * r;
        float4 v0 = pl0[row * 16 + txq];
        float4 v1 = pl1[row * 16 + txq];
        float rs0 = v0.x + v0.y + v0.z + v0.w;
        float rs1 = v1.x + v1.y + v1.z + v1.w;
        #pragma unroll
        for (int o = 8; o >= 1; o >>= 1) {
            rs0 += __shfl_xor_sync(0xffffffffu, rs0, o);
            rs1 += __shfl_xor_sync(0xffffffffu, rs1, o);
        }
        if (txq == 0) {
            sh_h[0][row] = rs0 * (1.0f / 64.0f);
            sh_h[1][row] = rs1 * (1.0f / 64.0f);
        }
        c00 += v0.x; c01 += v0.y; c02 += v0.z; c03 += v0.w;
        c10 += v1.x; c11 += v1.y; c12 += v1.z; c13 += v1.w;
    }
    cpart[0][ty][4 * txq + 0] = c00;
    cpart[0][ty][4 * txq + 1] = c01;
    cpart[0][ty][4 * txq + 2] = c02;
    cpart[0][ty][4 * txq + 3] = c03;
    cpart[1][ty][4 * txq + 0] = c10;
    cpart[1][ty][4 * txq + 1] = c11;
    cpart[1][ty][4 * txq + 2] = c12;
    cpart[1][ty][4 * txq + 3] = c13;
    __syncthreads();

    if (tid < 128) {
        int p   = tid >> 6;
        int col = tid & 63;
        float s = 0.f;
        #pragma unroll
        for (int t = 0; t < 16; t++) s += cpart[p][t][col];
        sh_w[p][col] = s * (1.0f / 64.0f);
    }
    __syncthreads();

    {
        int p = tid >> 7;       // 0 or 1
        int l = tid & 127;
        float val = (l < 64) ? sh_h[p][l] : sh_w[p][l - 64];
        g_y[(size_t)(bc0 + p) * 128 + l] = val;
    }
}

// ---------------- kernel 2: mid features y2 (16-wide load batches) ----------------
__global__ __launch_bounds__(256) void k2_mid(
    const float* __restrict__ ca_w1,
    const float* __restrict__ bn_g, const float* __restrict__ bn_b,
    const float* __restrict__ bn_m, const float* __restrict__ bn_v)
{
    int b_idx = blockIdx.x;
    int tid   = threadIdx.x;

    __shared__ float s_w[2048];       // ca_w1 (8 x 256)
    for (int i = tid; i < 2048; i += 256) s_w[i] = ca_w1[i];
    __syncthreads();

    // y2[m][l] = hswish(bn(sum_c ca_w1[m][c] * y[b][c][l]))
    int l  = tid & 127;
    int mg = tid >> 7;  // 0 or 1 -> m in [4*mg, 4*mg+4)
    float acc[4] = {0.f, 0.f, 0.f, 0.f};
    const float* yb = g_y + (size_t)b_idx * CC * 128 + l;

    for (int c0 = 0; c0 < CC; c0 += 16) {
        float yv[16];
        #pragma unroll
        for (int k = 0; k < 16; k++) yv[k] = yb[(c0 + k) * 128];
        #pragma unroll
        for (int k = 0; k < 16; k++) {
            #pragma unroll
            for (int mi = 0; mi < 4; mi++)
                acc[mi] += s_w[(mg * 4 + mi) * 256 + c0 + k] * yv[k];
        }
    }

    float* out = g_y2 + (size_t)b_idx * MIPD * 128;
    #pragma unroll
    for (int mi = 0; mi < 4; mi++) {
        int mm = mg * 4 + mi;
        float sc  = bn_g[mm] * rsqrtf(bn_v[mm] + 1e-5f);
        float val = (acc[mi] - bn_m[mm]) * sc + bn_b[mm];
        float t6  = fminf(fmaxf(val + 3.0f, 0.0f), 6.0f);
        out[mm * 128 + l] = val * t6 * (1.0f / 6.0f);
    }
}

// ---------------- kernel 3: attention + weighted pool (4 planes/block) ----------------
__global__ __launch_bounds__(256) void k3_wpool(
    const float* __restrict__ x,
    const float* __restrict__ ca_wh, const float* __restrict__ ca_ww)
{
    int b_idx = blockIdx.x >> 6;            // 32 b
    int c0    = (blockIdx.x & 63) * 4;      // 64 groups of 4 channels
    int tid   = threadIdx.x;

    __shared__ float s_y2[MIPD * 128];
    __shared__ float s_a[4][128];           // per plane: [0:64]=a_h, [64:128]=a_w
    __shared__ float red[4][8];

    // stage y2[b] (4KB)
    {
        const float* src = g_y2 + (size_t)b_idx * MIPD * 128;
        #pragma unroll
        for (int i = 0; i < 4; i++)
            s_y2[tid + 256 * i] = src[tid + 256 * i];
    }
    __syncthreads();

    // attention for 4 channels: 512 values, 2 per thread (full warps, no shuffle)
    #pragma unroll
    for (int rep = 0; rep < 2; rep++) {
        int idx = tid + 256 * rep;          // 0..511
        int p   = idx >> 7;                 // plane 0..3
        int l   = idx & 127;
        int c   = c0 + p;
        const float* wrow = (l < 64) ? (ca_wh + c * MIPD) : (ca_ww + c * MIPD);
        float s = 0.f;
        #pragma unroll
        for (int m = 0; m < MIPD; m++)
            s += __ldg(wrow + m) * s_y2[m * 128 + l];
        s_a[p][l] = 1.0f / (1.0f + __expf(-s));
    }
    __syncthreads();

    int txq = tid & 15;
    int ty  = tid >> 4;
    const float4* pl[4];
    #pragma unroll
    for (int p = 0; p < 4; p++)
        pl[p] = reinterpret_cast<const float4*>(
                    x + ((size_t)b_idx * CC + c0 + p) * (HH * WW));

    float aw[4][4];
    #pragma unroll
    for (int p = 0; p < 4; p++)
        #pragma unroll
        for (int i = 0; i < 4; i++)
            aw[p][i] = s_a[p][64 + 4 * txq + i];

    float acc[4] = {0.f, 0.f, 0.f, 0.f};
    #pragma unroll
    for (int r = 0; r < 4; r++) {
        int row = ty + 16 * r;
        #pragma unroll
        for (int p = 0; p < 4; p++) {
            float4 v = pl[p][row * 16 + txq];
            acc[p] += s_a[p][row] *
                      (v.x * aw[p][0] + v.y * aw[p][1] + v.z * aw[p][2] + v.w * aw[p][3]);
        }
    }
    #pragma unroll
    for (int p = 0; p < 4; p++) {
        float a = acc[p];
        #pragma unroll
        for (int o = 16; o >= 1; o >>= 1)
            a += __shfl_xor_sync(0xffffffffu, a, o);
        if ((tid & 31) == 0) red[p][tid >> 5] = a;
    }
    __syncthreads();
    if (tid < 4) {
        float s = 0.f;
        #pragma unroll
        for (int i = 0; i < 8; i++) s += red[tid][i];
        g_p[b_idx * CC + c0 + tid] = s * (1.0f / 4096.0f);
    }
}

// ---------------- helpers for kernel 4 ----------------
__device__ __forceinline__ float softplus_f(float x) {
    return fmaxf(x, 0.0f) + log1pf(__expf(-fabsf(x)));
}

// Exact port of LAPACK SLAEV2: matrix [[a,b],[b,c]].
__device__ void slaev2(float a, float b, float c,
                       float& rt1, float& rt2, float& cs1, float& sn1) {
    float sm  = a + c;
    float df  = a - c;
    float adf = fabsf(df);
    float tb  = b + b;
    float ab  = fabsf(tb);
    float acmx, acmn;
    if (fabsf(a) > fabsf(c)) { acmx = a; acmn = c; }
    else                     { acmx = c; acmn = a; }
    float rt;
    if      (adf > ab) { float q = ab / adf; rt = adf * sqrtf(1.0f + q * q); }
    else if (adf < ab) { float q = adf / ab; rt = ab  * sqrtf(1.0f + q * q); }
    else               { rt = ab * sqrtf(2.0f); }

    int sgn1;
    if (sm < 0.0f) {
        rt1 = 0.5f * (sm - rt); sgn1 = -1;
        rt2 = (acmx / rt1) * acmn - (b / rt1) * b;
    } else if (sm > 0.0f) {
        rt1 = 0.5f * (sm + rt); sgn1 = 1;
        rt2 = (acmx / rt1) * acmn - (b / rt1) * b;
    } else {
        rt1 = 0.5f * rt; rt2 = -0.5f * rt; sgn1 = 1;
    }

    float cs; int sgn2;
    if (df >= 0.0f) { cs = df + rt; sgn2 = 1; }
    else            { cs = df - rt; sgn2 = -1; }
    float acs = fabsf(cs);
    if (acs > ab) {
        float ct = -tb / cs;
        sn1 = 1.0f / sqrtf(1.0f + ct * ct);
        cs1 = ct * sn1;
    } else {
        if (ab == 0.0f) { cs1 = 1.0f; sn1 = 0.0f; }
        else {
            float tn = -cs / tb;
            cs1 = 1.0f / sqrtf(1.0f + tn * tn);
            sn1 = tn * cs1;
        }
    }
    if (sgn1 == sgn2) { float tn = cs1; cs1 = -sn1; sn1 = tn; }
}

// ---------------- kernel 4: MLP head + ellipse geometry ----------------
__global__ __launch_bounds__(256) void k4_head(
    const float* __restrict__ fc1_w,  const float* __restrict__ fc1_b,
    const float* __restrict__ bn1_g,  const float* __restrict__ bn1_b,
    const float* __restrict__ bn1_m,  const float* __restrict__ bn1_v,
    const float* __restrict__ fco_w,  const float* __restrict__ fco_b,
    const float* __restrict__ Kmat,   const float* __restrict__ iris_r,
    float* __restrict__ out)
{
    int b_idx = blockIdx.x;
    int tid   = threadIdx.x;

    __shared__ float s_p[HIDD];
    __shared__ float s_h[HIDD];
    __shared__ float s_raw[OUTD];

    s_p[tid] = g_p[b_idx * CC + tid];
    __syncthreads();

    // hdd = relu(bn1(p @ fc1_w^T + fc1_b))  -- 8 independent accumulators
    {
        const float4* wrow = reinterpret_cast<const float4*>(fc1_w + (size_t)tid * 256);
        const float4* pp   = reinterpret_cast<const float4*>(s_p);
        float a[8];
        #pragma unroll
        for (int i = 0; i < 8; i++) a[i] = 0.f;
        #pragma unroll
        for (int c4 = 0; c4 < 64; c4 += 8) {
            float4 w[8], p[8];
            #pragma unroll
            for (int i = 0; i < 8; i++) { w[i] = wrow[c4 + i]; p[i] = pp[c4 + i]; }
            #pragma unroll
            for (int i = 0; i < 8; i++)
                a[i] += w[i].x * p[i].x + w[i].y * p[i].y + w[i].z * p[i].z + w[i].w * p[i].w;
        }
        float acc = (((a[0] + a[1]) + (a[2] + a[3])) + ((a[4] + a[5]) + (a[6] + a[7])))
                    + fc1_b[tid];
        float sc  = bn1_g[tid] * rsqrtf(bn1_v[tid] + 1e-5f);
        float val = (acc - bn1_m[tid]) * sc + bn1_b[tid];
        s_h[tid] = fmaxf(val, 0.0f);
    }
    __syncthreads();

    // raw = hdd @ fc_out^T + b  -- whole warps 0-3 (full-mask shuffles safe);
    // rows 14,15 phantom with clamped loads, result discarded.
    if (tid < 128) {
        int r  = tid >> 3;                    // 0..15 (14,15 phantom)
        int j  = tid & 7;
        int rc = (r < OUTD) ? r : (OUTD - 1);
        const float4* wrow = reinterpret_cast<const float4*>(fco_w + (size_t)rc * 256);
        const float4* hh   = reinterpret_cast<const float4*>(s_h);
        float acc = 0.f;
        #pragma unroll
        for (int q = 0; q < 8; q++) {
            float4 w = wrow[j * 8 + q];
            float4 h = hh[j * 8 + q];
            acc += w.x * h.x + w.y * h.y + w.z * h.z + w.w * h.w;
        }
        acc += __shfl_xor_sync(0xffffffffu, acc, 1);
        acc += __shfl_xor_sync(0xffffffffu, acc, 2);
        acc += __shfl_xor_sync(0xffffffffu, acc, 4);
        if (j == 0 && r < OUTD) s_raw[r] = acc + fco_b[r];
    }
    __syncthreads();

    // geometry, one thread per ellipse e in {0,1}
    if (tid < 2) {
        const float* t  = s_raw + 7 * tid;
        const float* Kb = Kmat + b_idx * 9;
        float R = iris_r[b_idx];
        int be = b_idx * 2 + tid;

        float cx = t[0], cy = t[1];
        float ea = softplus_f(t[2]) + 1e-6f;
        float eb = softplus_f(t[3]) + 1e-6f;
        float n45 = sqrtf(t[4] * t[4] + t[5] * t[5]);
        float cth = t[4] / (n45 + 1e-8f);
        float sth = t[5] / (n45 + 1e-8f);
        float e7 = __expf(2.0f * t[6]);
        float delta = 0.3f * ((e7 - 1.0f) / (e7 + 1.0f));   // tanh

        out[be * 6 + 0] = cx;  out[be * 6 + 1] = cy;
        out[be * 6 + 2] = ea;  out[be * 6 + 3] = eb;
        out[be * 6 + 4] = cth; out[be * 6 + 5] = sth;
        out[384 + be] = delta;

        // cos(atan2(sth,cth)) == cth, sin == sth (unit vector) -> skip trig
        float ct = cth, st = sth;
        float ia2 = 1.0f / (ea * ea), ib2 = 1.0f / (eb * eb);
        float A11 = ct * ct * ia2 + st * st * ib2;
        float A22 = st * st * ia2 + ct * ct * ib2;
        float A12 = ct * st * (ia2 - ib2);
        float ax  = A11 * cx + A12 * cy;
        float ay  = A12 * cx + A22 * cy;
        float cAc = A11 * cx * cx + 2.0f * A12 * cx * cy + A22 * cy * cy;

        float Cm[3][3] = {{A11, A12, -ax}, {A12, A22, -ay}, {-ax, -ay, cAc - 1.0f}};
        float Kl[3][3];
        #pragma unroll
        for (int r = 0; r < 3; r++)
            #pragma unroll
            for (int c = 0; c < 3; c++)
                Kl[r][c] = Kb[r * 3 + c];

        float T[3][3], Cn[3][3];
        #pragma unroll
        for (int j = 0; j < 3; j++)
            #pragma unroll
            for (int l = 0; l < 3; l++)
                T[j][l] = Cm[j][0] * Kl[0][l] + Cm[j][1] * Kl[1][l] + Cm[j][2] * Kl[2][l];
        #pragma unroll
        for (int i = 0; i < 3; i++)
            #pragma unroll
            for (int l = 0; l < 3; l++)
                Cn[i][l] = Kl[0][i] * T[0][l] + Kl[1][i] * T[1][l] + Kl[2][i] * T[2][l];

        float u0 = Cn[0][2], u1 = Cn[1][2];
        float det = Cn[0][0] * Cn[1][1] - Cn[0][1] * Cn[1][0];
        float mu0 = (-u0 * Cn[1][1] + u1 * Cn[0][1]) / det;
        float mu1 = (-u1 * Cn[0][0] + u0 * Cn[1][0]) / det;

        float aa = Cn[0][0];
        float bb = 0.5f * (Cn[0][1] + Cn[1][0]);
        float cc = Cn[1][1];
        float rt1, rt2, cs1, sn1;
        slaev2(aa, bb, cc, rt1, rt2, cs1, sn1);
        float lam0, lam1, v0, v1;
        if (rt1 >= rt2) { lam0 = rt2; lam1 = rt1; v0 = -sn1; v1 = cs1; }
        else            { lam0 = rt1; lam1 = rt2; v0 = cs1;  v1 = sn1; }

        float a_n = 1.0f / sqrtf(fmaxf(lam0, 1e-12f));
        float b_n = 1.0f / sqrtf(fmaxf(lam1, 1e-12f));
        a_n = fmaxf(a_n, 1e-6f);

        float z = fminf(fmaxf(R / a_n, 0.5f), 1000.0f);
        float rn = sqrtf(mu0 * mu0 + mu1 * mu1 + 1.0f) + 1e-8f;
        float ic0 = (mu0 / rn) * z, ic1 = (mu1 / rn) * z, ic2 = (1.0f / rn) * z;

        float ctl = fminf(fmaxf(b_n / a_n, 0.0f), 1.0f);
        float stl = sqrtf(fmaxf(1.0f - ctl * ctl, 0.0f));

        // k = normalize((cos(theta_n), sin(theta_n), 0)) == (v0, v1) normalized
        float kn = sqrtf(v0 * v0 + v1 * v1) + 1e-8f;
        float kx = v0 / kn, ky = v1 / kn;

        float nx = ky * stl, ny = -kx * stl, nz = ctl;
        float nn = sqrtf(nx * nx + ny * ny + nz * nz) + 1e-8f;
        nx /= nn; ny /= nn; nz /= nn;

        out[448 + be * 3 + 0] = ic0;
        out[448 + be * 3 + 1] = ic1;
        out[448 + be * 3 + 2] = ic2;
        out[640 + be * 3 + 0] = nx;
        out[640 + be * 3 + 1] = ny;
        out[640 + be * 3 + 2] = nz;
        out[832 + be * 3 + 0] = ic0 + delta * nx;
        out[832 + be * 3 + 1] = ic1 + delta * ny;
        out[832 + be * 3 + 2] = ic2 + delta * nz;
        out[1024 + be] = z;
    }
}

// ---------------- launch ----------------
extern "C" void kernel_launch(void* const* d_in, const int* in_sizes, int n_in,
                              void* d_out, int out_size) {
    const float* x      = (const float*)d_in[0];
    const float* K      = (const float*)d_in[1];
    const float* iris_r = (const float*)d_in[2];
    const float* ca_w1  = (const float*)d_in[3];
    const float* ca_g   = (const float*)d_in[4];
    const float* ca_b   = (const float*)d_in[5];
    const float* ca_m   = (const float*)d_in[6];
    const float* ca_v   = (const float*)d_in[7];
    const float* ca_wh  = (const float*)d_in[8];
    const float* ca_ww  = (const float*)d_in[9];
    const float* fc1_w  = (const float*)d_in[10];
    const float* fc1_b  = (const float*)d_in[11];
    const float* bn1_g  = (const float*)d_in[12];
    const float* bn1_b  = (const float*)d_in[13];
    const float* bn1_m  = (const float*)d_in[14];
    const float* bn1_v  = (const float*)d_in[15];
    const float* fco_w  = (const float*)d_in[16];
    const float* fco_b  = (const float*)d_in[17];
    float* out = (float*)d_out;

    k1_pool<<<BB * CC / 2, 256>>>(x);
    k2_mid<<<BB, 256>>>(ca_w1, ca_g, ca_b, ca_m, ca_v);
    k3_wpool<<<BB * CC / 4, 256>>>(x, ca_wh, ca_ww);
    k4_head<<<BB, 256>>>(fc1_w, fc1_b, bn1_g, bn1_b, bn1_m, bn1_v,
                         fco_w, fco_b, K, iris_r, out);
}

// round 8
// speedup vs baseline: 1.3015x; 1.0046x over previous
#include <cuda_runtime.h>
#include <math.h>

#define BB   32
#define CC   256
#define HH   64
#define WW   64
#define MIPD 8
#define HIDD 256
#define OUTD 14

// ---------------- scratch (no allocations allowed) ----------------
__device__ float g_y  [BB * CC * 128];   // [b][c][l]  l: 0..63 = xh, 64..127 = xw
__device__ float g_y2 [BB * MIPD * 128]; // [b][m][l]  post-bn-hswish mid features
__device__ float g_p  [BB * CC];         // [b][c]

// ---------------- kernel 1: per-plane row/col means (2 planes/block) ----------------
__global__ __launch_bounds__(256) void k1_pool(const float* __restrict__ x) {
    int bc0 = blockIdx.x * 2;
    int tid = threadIdx.x;
    int txq = tid & 15;                         // float4 index within row
    int ty  = tid >> 4;                         // 0..15

    const float4* pl0 = reinterpret_cast<const float4*>(x + (size_t)bc0 * (HH * WW));
    const float4* pl1 = pl0 + 1024;

    __shared__ float sh_h[2][64];
    __shared__ float sh_w[2][64];
    __shared__ float cpart[2][16][64];

    float c00 = 0.f, c01 = 0.f, c02 = 0.f, c03 = 0.f;
    float c10 = 0.f, c11 = 0.f, c12 = 0.f, c13 = 0.f;
    #pragma unroll
    for (int r = 0; r < 4; r++) {
        int row = ty + 16 * r;
        float4 v0 = pl0[row * 16 + txq];
        float4 v1 = pl1[row * 16 + txq];
        float rs0 = v0.x + v0.y + v0.z + v0.w;
        float rs1 = v1.x + v1.y + v1.z + v1.w;
        #pragma unroll
        for (int o = 8; o >= 1; o >>= 1) {
            rs0 += __shfl_xor_sync(0xffffffffu, rs0, o);
            rs1 += __shfl_xor_sync(0xffffffffu, rs1, o);
        }
        if (txq == 0) {
            sh_h[0][row] = rs0 * (1.0f / 64.0f);
            sh_h[1][row] = rs1 * (1.0f / 64.0f);
        }
        c00 += v0.x; c01 += v0.y; c02 += v0.z; c03 += v0.w;
        c10 += v1.x; c11 += v1.y; c12 += v1.z; c13 += v1.w;
    }
    cpart[0][ty][4 * txq + 0] = c00;
    cpart[0][ty][4 * txq + 1] = c01;
    cpart[0][ty][4 * txq + 2] = c02;
    cpart[0][ty][4 * txq + 3] = c03;
    cpart[1][ty][4 * txq + 0] = c10;
    cpart[1][ty][4 * txq + 1] = c11;
    cpart[1][ty][4 * txq + 2] = c12;
    cpart[1][ty][4 * txq + 3] = c13;
    __syncthreads();

    if (tid < 128) {
        int p   = tid >> 6;
        int col = tid & 63;
        float s = 0.f;
        #pragma unroll
        for (int t = 0; t < 16; t++) s += cpart[p][t][col];
        sh_w[p][col] = s * (1.0f / 64.0f);
    }
    __syncthreads();

    {
        int p = tid >> 7;       // 0 or 1
        int l = tid & 127;
        float val = (l < 64) ? sh_h[p][l] : sh_w[p][l - 64];
        g_y[(size_t)(bc0 + p) * 128 + l] = val;
    }
}

// ---------------- kernel 2: mid features y2 (16-wide load batches) ----------------
__global__ __launch_bounds__(256) void k2_mid(
    const float* __restrict__ ca_w1,
    const float* __restrict__ bn_g, const float* __restrict__ bn_b,
    const float* __restrict__ bn_m, const float* __restrict__ bn_v)
{
    int b_idx = blockIdx.x;
    int tid   = threadIdx.x;

    __shared__ float s_w[2048];       // ca_w1 (8 x 256)
    for (int i = tid; i < 2048; i += 256) s_w[i] = ca_w1[i];
    __syncthreads();

    // y2[m][l] = hswish(bn(sum_c ca_w1[m][c] * y[b][c][l]))
    int l  = tid & 127;
    int mg = tid >> 7;  // 0 or 1 -> m in [4*mg, 4*mg+4)
    float acc[4] = {0.f, 0.f, 0.f, 0.f};
    const float* yb = g_y + (size_t)b_idx * CC * 128 + l;

    for (int c0 = 0; c0 < CC; c0 += 16) {
        float yv[16];
        #pragma unroll
        for (int k = 0; k < 16; k++) yv[k] = yb[(c0 + k) * 128];
        #pragma unroll
        for (int k = 0; k < 16; k++) {
            #pragma unroll
            for (int mi = 0; mi < 4; mi++)
                acc[mi] += s_w[(mg * 4 + mi) * 256 + c0 + k] * yv[k];
        }
    }

    float* out = g_y2 + (size_t)b_idx * MIPD * 128;
    #pragma unroll
    for (int mi = 0; mi < 4; mi++) {
        int mm = mg * 4 + mi;
        float sc  = bn_g[mm] * rsqrtf(bn_v[mm] + 1e-5f);
        float val = (acc[mi] - bn_m[mm]) * sc + bn_b[mm];
        float t6  = fminf(fmaxf(val + 3.0f, 0.0f), 6.0f);
        out[mm * 128 + l] = val * t6 * (1.0f / 6.0f);
    }
}

// ---------------- kernel 3: attention + weighted pool (4 planes/block) ----------------
__global__ __launch_bounds__(256) void k3_wpool(
    const float* __restrict__ x,
    const float* __restrict__ ca_wh, const float* __restrict__ ca_ww)
{
    int b_idx = blockIdx.x >> 6;            // 32 b
    int c0    = (blockIdx.x & 63) * 4;      // 64 groups of 4 channels
    int tid   = threadIdx.x;

    __shared__ float s_y2[MIPD * 128];
    __shared__ float s_a[4][128];           // per plane: [0:64]=a_h, [64:128]=a_w
    __shared__ float red[4][8];

    // stage y2[b] (4KB)
    {
        const float* src = g_y2 + (size_t)b_idx * MIPD * 128;
        #pragma unroll
        for (int i = 0; i < 4; i++)
            s_y2[tid + 256 * i] = src[tid + 256 * i];
    }
    __syncthreads();

    // attention for 4 channels: 512 values, 2 per thread (full warps, no shuffle)
    #pragma unroll
    for (int rep = 0; rep < 2; rep++) {
        int idx = tid + 256 * rep;          // 0..511
        int p   = idx >> 7;                 // plane 0..3
        int l   = idx & 127;
        int c   = c0 + p;
        const float* wrow = (l < 64) ? (ca_wh + c * MIPD) : (ca_ww + c * MIPD);
        float s = 0.f;
        #pragma unroll
        for (int m = 0; m < MIPD; m++)
            s += __ldg(wrow + m) * s_y2[m * 128 + l];
        s_a[p][l] = 1.0f / (1.0f + __expf(-s));
    }
    __syncthreads();

    int txq = tid & 15;
    int ty  = tid >> 4;
    const float4* pl[4];
    #pragma unroll
    for (int p = 0; p < 4; p++)
        pl[p] = reinterpret_cast<const float4*>(
                    x + ((size_t)b_idx * CC + c0 + p) * (HH * WW));

    float aw[4][4];
    #pragma unroll
    for (int p = 0; p < 4; p++)
        #pragma unroll
        for (int i = 0; i < 4; i++)
            aw[p][i] = s_a[p][64 + 4 * txq + i];

    float acc[4] = {0.f, 0.f, 0.f, 0.f};
    #pragma unroll
    for (int r = 0; r < 4; r++) {
        int row = ty + 16 * r;
        #pragma unroll
        for (int p = 0; p < 4; p++) {
            float4 v = pl[p][row * 16 + txq];
            acc[p] += s_a[p][row] *
                      (v.x * aw[p][0] + v.y * aw[p][1] + v.z * aw[p][2] + v.w * aw[p][3]);
        }
    }
    #pragma unroll
    for (int p = 0; p < 4; p++) {
        float a = acc[p];
        #pragma unroll
        for (int o = 16; o >= 1; o >>= 1)
            a += __shfl_xor_sync(0xffffffffu, a, o);
        if ((tid & 31) == 0) red[p][tid >> 5] = a;
    }
    __syncthreads();
    if (tid < 4) {
        float s = 0.f;
        #pragma unroll
        for (int i = 0; i < 8; i++) s += red[tid][i];
        g_p[b_idx * CC + c0 + tid] = s * (1.0f / 4096.0f);
    }
}

// ---------------- helpers for kernel 4 ----------------
__device__ __forceinline__ float softplus_f(float x) {
    return fmaxf(x, 0.0f) + log1pf(__expf(-fabsf(x)));
}

// Exact port of LAPACK SLAEV2: matrix [[a,b],[b,c]].
__device__ void slaev2(float a, float b, float c,
                       float& rt1, float& rt2, float& cs1, float& sn1) {
    float sm  = a + c;
    float df  = a - c;
    float adf = fabsf(df);
    float tb  = b + b;
    float ab  = fabsf(tb);
    float acmx, acmn;
    if (fabsf(a) > fabsf(c)) { acmx = a; acmn = c; }
    else                     { acmx = c; acmn = a; }
    float rt;
    if      (adf > ab) { float q = ab / adf; rt = adf * sqrtf(1.0f + q * q); }
    else if (adf < ab) { float q = adf / ab; rt = ab  * sqrtf(1.0f + q * q); }
    else               { rt = ab * sqrtf(2.0f); }

    int sgn1;
    if (sm < 0.0f) {
        rt1 = 0.5f * (sm - rt); sgn1 = -1;
        rt2 = (acmx / rt1) * acmn - (b / rt1) * b;
    } else if (sm > 0.0f) {
        rt1 = 0.5f * (sm + rt); sgn1 = 1;
        rt2 = (acmx / rt1) * acmn - (b / rt1) * b;
    } else {
        rt1 = 0.5f * rt; rt2 = -0.5f * rt; sgn1 = 1;
    }

    float cs; int sgn2;
    if (df >= 0.0f) { cs = df + rt; sgn2 = 1; }
    else            { cs = df - rt; sgn2 = -1; }
    float acs = fabsf(cs);
    if (acs > ab) {
        float ct = -tb / cs;
        sn1 = 1.0f / sqrtf(1.0f + ct * ct);
        cs1 = ct * sn1;
    } else {
        if (ab == 0.0f) { cs1 = 1.0f; sn1 = 0.0f; }
        else {
            float tn = -cs / tb;
            cs1 = 1.0f / sqrtf(1.0f + tn * tn);
            sn1 = tn * cs1;
        }
    }
    if (sgn1 == sgn2) { float tn = cs1; cs1 = -sn1; sn1 = tn; }
}

// ---------------- kernel 4: MLP head + ellipse geometry ----------------
__global__ __launch_bounds__(256) void k4_head(
    const float* __restrict__ fc1_w,  const float* __restrict__ fc1_b,
    const float* __restrict__ bn1_g,  const float* __restrict__ bn1_b,
    const float* __restrict__ bn1_m,  const float* __restrict__ bn1_v,
    const float* __restrict__ fco_w,  const float* __restrict__ fco_b,
    const float* __restrict__ Kmat,   const float* __restrict__ iris_r,
    float* __restrict__ out)
{
    int b_idx = blockIdx.x;
    int tid   = threadIdx.x;

    __shared__ float s_p[HIDD];
    __shared__ float s_h[HIDD];
    __shared__ float s_raw[OUTD];

    s_p[tid] = g_p[b_idx * CC + tid];
    __syncthreads();

    // hdd = relu(bn1(p @ fc1_w^T + fc1_b))  -- 8 independent accumulators
    {
        const float4* wrow = reinterpret_cast<const float4*>(fc1_w + (size_t)tid * 256);
        const float4* pp   = reinterpret_cast<const float4*>(s_p);
        float a[8];
        #pragma unroll
        for (int i = 0; i < 8; i++) a[i] = 0.f;
        #pragma unroll
        for (int c4 = 0; c4 < 64; c4 += 8) {
            float4 w[8], p[8];
            #pragma unroll
            for (int i = 0; i < 8; i++) { w[i] = wrow[c4 + i]; p[i] = pp[c4 + i]; }
            #pragma unroll
            for (int i = 0; i < 8; i++)
                a[i] += w[i].x * p[i].x + w[i].y * p[i].y + w[i].z * p[i].z + w[i].w * p[i].w;
        }
        float acc = (((a[0] + a[1]) + (a[2] + a[3])) + ((a[4] + a[5]) + (a[6] + a[7])))
                    + fc1_b[tid];
        float sc  = bn1_g[tid] * rsqrtf(bn1_v[tid] + 1e-5f);
        float val = (acc - bn1_m[tid]) * sc + bn1_b[tid];
        s_h[tid] = fmaxf(val, 0.0f);
    }
    __syncthreads();

    // raw = hdd @ fc_out^T + b  -- whole warps 0-3 (full-mask shuffles safe);
    // rows 14,15 phantom with clamped loads, result discarded.
    if (tid < 128) {
        int r  = tid >> 3;                    // 0..15 (14,15 phantom)
        int j  = tid & 7;
        int rc = (r < OUTD) ? r : (OUTD - 1);
        const float4* wrow = reinterpret_cast<const float4*>(fco_w + (size_t)rc * 256);
        const float4* hh   = reinterpret_cast<const float4*>(s_h);
        float acc = 0.f;
        #pragma unroll
        for (int q = 0; q < 8; q++) {
            float4 w = wrow[j * 8 + q];
            float4 h = hh[j * 8 + q];
            acc += w.x * h.x + w.y * h.y + w.z * h.z + w.w * h.w;
        }
        acc += __shfl_xor_sync(0xffffffffu, acc, 1);
        acc += __shfl_xor_sync(0xffffffffu, acc, 2);
        acc += __shfl_xor_sync(0xffffffffu, acc, 4);
        if (j == 0 && r < OUTD) s_raw[r] = acc + fco_b[r];
    }
    __syncthreads();

    // geometry, one thread per ellipse e in {0,1}
    if (tid < 2) {
        const float* t  = s_raw + 7 * tid;
        const float* Kb = Kmat + b_idx * 9;
        float R = iris_r[b_idx];
        int be = b_idx * 2 + tid;

        float cx = t[0], cy = t[1];
        float ea = softplus_f(t[2]) + 1e-6f;
        float eb = softplus_f(t[3]) + 1e-6f;
        float n45 = sqrtf(t[4] * t[4] + t[5] * t[5]);
        float cth = t[4] / (n45 + 1e-8f);
        float sth = t[5] / (n45 + 1e-8f);
        float e7 = __expf(2.0f * t[6]);
        float delta = 0.3f * ((e7 - 1.0f) / (e7 + 1.0f));   // tanh

        out[be * 6 + 0] = cx;  out[be * 6 + 1] = cy;
        out[be * 6 + 2] = ea;  out[be * 6 + 3] = eb;
        out[be * 6 + 4] = cth; out[be * 6 + 5] = sth;
        out[384 + be] = delta;

        // cos(atan2(sth,cth)) == cth, sin == sth (unit vector) -> skip trig
        float ct = cth, st = sth;
        float ia2 = 1.0f / (ea * ea), ib2 = 1.0f / (eb * eb);
        float A11 = ct * ct * ia2 + st * st * ib2;
        float A22 = st * st * ia2 + ct * ct * ib2;
        float A12 = ct * st * (ia2 - ib2);
        float ax  = A11 * cx + A12 * cy;
        float ay  = A12 * cx + A22 * cy;
        float cAc = A11 * cx * cx + 2.0f * A12 * cx * cy + A22 * cy * cy;

        float Cm[3][3] = {{A11, A12, -ax}, {A12, A22, -ay}, {-ax, -ay, cAc - 1.0f}};
        float Kl[3][3];
        #pragma unroll
        for (int r = 0; r < 3; r++)
            #pragma unroll
            for (int c = 0; c < 3; c++)
                Kl[r][c] = Kb[r * 3 + c];

        float T[3][3], Cn[3][3];
        #pragma unroll
        for (int j = 0; j < 3; j++)
            #pragma unroll
            for (int l = 0; l < 3; l++)
                T[j][l] = Cm[j][0] * Kl[0][l] + Cm[j][1] * Kl[1][l] + Cm[j][2] * Kl[2][l];
        #pragma unroll
        for (int i = 0; i < 3; i++)
            #pragma unroll
            for (int l = 0; l < 3; l++)
                Cn[i][l] = Kl[0][i] * T[0][l] + Kl[1][i] * T[1][l] + Kl[2][i] * T[2][l];

        float u0 = Cn[0][2], u1 = Cn[1][2];
        float det = Cn[0][0] * Cn[1][1] - Cn[0][1] * Cn[1][0];
        float mu0 = (-u0 * Cn[1][1] + u1 * Cn[0][1]) / det;
        float mu1 = (-u1 * Cn[0][0] + u0 * Cn[1][0]) / det;

        float aa = Cn[0][0];
        float bb = 0.5f * (Cn[0][1] + Cn[1][0]);
        float cc = Cn[1][1];
        float rt1, rt2, cs1, sn1;
        slaev2(aa, bb, cc, rt1, rt2, cs1, sn1);
        float lam0, lam1, v0, v1;
        if (rt1 >= rt2) { lam0 = rt2; lam1 = rt1; v0 = -sn1; v1 = cs1; }
        else            { lam0 = rt1; lam1 = rt2; v0 = cs1;  v1 = sn1; }

        float a_n = 1.0f / sqrtf(fmaxf(lam0, 1e-12f));
        float b_n = 1.0f / sqrtf(fmaxf(lam1, 1e-12f));
        a_n = fmaxf(a_n, 1e-6f);

        float z = fminf(fmaxf(R / a_n, 0.5f), 1000.0f);
        float rn = sqrtf(mu0 * mu0 + mu1 * mu1 + 1.0f) + 1e-8f;
        float ic0 = (mu0 / rn) * z, ic1 = (mu1 / rn) * z, ic2 = (1.0f / rn) * z;

        float ctl = fminf(fmaxf(b_n / a_n, 0.0f), 1.0f);
        float stl = sqrtf(fmaxf(1.0f - ctl * ctl, 0.0f));

        // k = normalize((cos(theta_n), sin(theta_n), 0)) == (v0, v1) normalized
        float kn = sqrtf(v0 * v0 + v1 * v1) + 1e-8f;
        float kx = v0 / kn, ky = v1 / kn;

        float nx = ky * stl, ny = -kx * stl, nz = ctl;
        float nn = sqrtf(nx * nx + ny * ny + nz * nz) + 1e-8f;
        nx /= nn; ny /= nn; nz /= nn;

        out[448 + be * 3 + 0] = ic0;
        out[448 + be * 3 + 1] = ic1;
        out[448 + be * 3 + 2] = ic2;
        out[640 + be * 3 + 0] = nx;
        out[640 + be * 3 + 1] = ny;
        out[640 + be * 3 + 2] = nz;
        out[832 + be * 3 + 0] = ic0 + delta * nx;
        out[832 + be * 3 + 1] = ic1 + delta * ny;
        out[832 + be * 3 + 2] = ic2 + delta * nz;
        out[1024 + be] = z;
    }
}

// ---------------- launch ----------------
extern "C" void kernel_launch(void* const* d_in, const int* in_sizes, int n_in,
                              void* d_out, int out_size) {
    const float* x      = (const float*)d_in[0];
    const float* K      = (const float*)d_in[1];
    const float* iris_r = (const float*)d_in[2];
    const float* ca_w1  = (const float*)d_in[3];
    const float* ca_g   = (const float*)d_in[4];
    const float* ca_b   = (const float*)d_in[5];
    const float* ca_m   = (const float*)d_in[6];
    const float* ca_v   = (const float*)d_in[7];
    const float* ca_wh  = (const float*)d_in[8];
    const float* ca_ww  = (const float*)d_in[9];
    const float* fc1_w  = (const float*)d_in[10];
    const float* fc1_b  = (const float*)d_in[11];
    const float* bn1_g  = (const float*)d_in[12];
    const float* bn1_b  = (const float*)d_in[13];
    const float* bn1_m  = (const float*)d_in[14];
    const float* bn1_v  = (const float*)d_in[15];
    const float* fco_w  = (const float*)d_in[16];
    const float* fco_b  = (const float*)d_in[17];
    float* out = (float*)d_out;

    k1_pool<<<BB * CC / 2, 256>>>(x);
    k2_mid<<<BB, 256>>>(ca_w1, ca_g, ca_b, ca_m, ca_v);
    k3_wpool<<<BB * CC / 4, 256>>>(x, ca_wh, ca_ww);
    k4_head<<<BB, 256>>>(fc1_w, fc1_b, bn1_g, bn1_b, bn1_m, bn1_v,
                         fco_w, fco_b, K, iris_r, out);
}